// round 3
// baseline (speedup 1.0000x reference)
#include <cuda_runtime.h>
#include <math.h>

// Scratch (no device allocations allowed)
__device__ float g_s[32 * 512];     // channel means
__device__ float g_gate[32 * 512];  // sigmoid gate

#define BATCH 32
#define CIN 512
#define HID 64
#define PLANE 4096           // 64*64
#define NKNOT 12             // GRID_SIZE + 2*SPLINE_ORDER + 1
#define NBASE 8              // GRID_SIZE + SPLINE_ORDER

__device__ __forceinline__ float siluf(float v) {
    return v / (1.0f + __expf(-v));
}

// Cox-de Boor, mirroring the reference recursion. t: 12 knots -> 8 order-3 bases.
__device__ __forceinline__ void bspline8(float x, const float* t, float* out) {
    float b[11];
#pragma unroll
    for (int j = 0; j < 11; j++)
        b[j] = (x >= t[j] && x < t[j + 1]) ? 1.0f : 0.0f;
#pragma unroll
    for (int k = 1; k <= 3; k++) {
#pragma unroll
        for (int j = 0; j < 10; j++) {
            if (j <= 10 - k) {
                float left  = (x - t[j]) / (t[j + k] - t[j]) * b[j];
                float right = (t[j + k + 1] - x) / (t[j + k + 1] - t[j + 1]) * b[j + 1];
                b[j] = left + right;
            }
        }
    }
#pragma unroll
    for (int j = 0; j < NBASE; j++) out[j] = b[j];
}

// ---------------------------------------------------------------------------
// Kernel 1: per-(b,c) plane mean. One block per plane, 256 threads, float4.
// ---------------------------------------------------------------------------
__global__ void __launch_bounds__(256) mean_kernel(const float4* __restrict__ x,
                                                   float* __restrict__ s_out) {
    const int plane = blockIdx.x;
    const float4* p = x + (size_t)plane * (PLANE / 4);
    float4 v0 = p[threadIdx.x];
    float4 v1 = p[256 + threadIdx.x];
    float4 v2 = p[512 + threadIdx.x];
    float4 v3 = p[768 + threadIdx.x];
    float sum = ((v0.x + v0.y) + (v0.z + v0.w)) + ((v1.x + v1.y) + (v1.z + v1.w))
              + ((v2.x + v2.y) + (v2.z + v2.w)) + ((v3.x + v3.y) + (v3.z + v3.w));
#pragma unroll
    for (int off = 16; off >= 1; off >>= 1)
        sum += __shfl_xor_sync(0xffffffffu, sum, off);

    __shared__ float ws[8];
    if ((threadIdx.x & 31) == 0) ws[threadIdx.x >> 5] = sum;
    __syncthreads();
    if (threadIdx.x == 0) {
        float tot = 0.0f;
#pragma unroll
        for (int w = 0; w < 8; w++) tot += ws[w];
        float m = tot * (1.0f / (float)PLANE);
        if (isnan(m)) m = 0.0f;
        m = fminf(fmaxf(m, -3.402823466e38f), 3.402823466e38f);
        s_out[plane] = m;
    }
}

// ---------------------------------------------------------------------------
// Kernel 2: whole KAN (prep + layer1 + layer2 + sigmoid). 32 blocks x 512 thr.
// ---------------------------------------------------------------------------
__global__ void __launch_bounds__(512) kan_fused_kernel(
    const float* __restrict__ s_in,
    const float* __restrict__ grid1, const float* __restrict__ bw1,
    const float* __restrict__ sw1,  const float* __restrict__ sc1,
    const float* __restrict__ grid2, const float* __restrict__ bw2,
    const float* __restrict__ sw2,  const float* __restrict__ sc2,
    float* __restrict__ gate) {

    __shared__ float sh_silu[CIN];
    __shared__ float sh_bT[NBASE][CIN];   // transposed bases (conflict-free reads)
    __shared__ float sh_y1[HID];
    __shared__ float sh_h2[HID];          // silu(silu(layer1 out))
    __shared__ float sh_b2[HID][NBASE];   // layer-2 bases

    const int b = blockIdx.x;
    const int tid = threadIdx.x;

    // ---- prep: silu(s) and bases(s) per input feature (thread = c) ----
    {
        float s = s_in[b * CIN + tid];
        sh_silu[tid] = siluf(s);
        float t[NKNOT];
#pragma unroll
        for (int j = 0; j < NKNOT; j++) t[j] = grid1[tid * NKNOT + j];
        float bb[NBASE];
        bspline8(s, t, bb);
#pragma unroll
        for (int k = 0; k < NBASE; k++) sh_bT[k][tid] = bb[k];
    }
    __syncthreads();

    // ---- layer 1: 64 outputs, 8 lanes each, coalesced sw1 reads ----
    {
        const int o = tid >> 3;   // 0..63
        const int l = tid & 7;    // 0..7
        const float4* sw4  = (const float4*)(sw1 + (size_t)o * CIN * NBASE);
        const float*  bwrow = bw1 + o * CIN;
        const float*  scrow = sc1 + o * CIN;

        float acc = 0.0f;
#pragma unroll 8
        for (int s = 0; s < CIN / 8; s++) {
            int i = l + 8 * s;
            float4 wa = sw4[i * 2];
            float4 wb = sw4[i * 2 + 1];
            float sp = sh_bT[0][i] * wa.x + sh_bT[1][i] * wa.y
                     + sh_bT[2][i] * wa.z + sh_bT[3][i] * wa.w
                     + sh_bT[4][i] * wb.x + sh_bT[5][i] * wb.y
                     + sh_bT[6][i] * wb.z + sh_bT[7][i] * wb.w;
            acc += sh_silu[i] * bwrow[i] + sp * scrow[i];
        }
#pragma unroll
        for (int off = 4; off >= 1; off >>= 1)
            acc += __shfl_xor_sync(0xffffffffu, acc, off);
        if (l == 0) sh_y1[o] = acc;
    }
    __syncthreads();

    // ---- inter-layer: silu + layer-2 bases (threads 0..63) ----
    if (tid < HID) {
        float h = siluf(sh_y1[tid]);
        sh_h2[tid] = siluf(h);
        float t[NKNOT];
#pragma unroll
        for (int j = 0; j < NKNOT; j++) t[j] = grid2[tid * NKNOT + j];
        float bb2[NBASE];
        bspline8(h, t, bb2);
#pragma unroll
        for (int k = 0; k < NBASE; k++) sh_b2[tid][k] = bb2[k];
    }
    __syncthreads();

    // ---- layer 2: one warp per output, 32 passes of 16 warps ----
    {
        const int wid = tid >> 5;   // 0..15
        const int lane = tid & 31;  // 0..31
        const int j0 = lane * 2;    // each lane covers j0, j0+1
#pragma unroll 2
        for (int p = 0; p < 32; p++) {
            const int c = p * 16 + wid;   // 0..511
            const float4* sw4 = (const float4*)(sw2 + (size_t)c * HID * NBASE);
            // lane reads 64B contiguous: j0*8 .. j0*8+15 floats
            float4 w0 = sw4[j0 * 2];
            float4 w1 = sw4[j0 * 2 + 1];
            float4 w2 = sw4[j0 * 2 + 2];
            float4 w3 = sw4[j0 * 2 + 3];
            float sp0 = sh_b2[j0][0] * w0.x + sh_b2[j0][1] * w0.y
                      + sh_b2[j0][2] * w0.z + sh_b2[j0][3] * w0.w
                      + sh_b2[j0][4] * w1.x + sh_b2[j0][5] * w1.y
                      + sh_b2[j0][6] * w1.z + sh_b2[j0][7] * w1.w;
            float sp1 = sh_b2[j0 + 1][0] * w2.x + sh_b2[j0 + 1][1] * w2.y
                      + sh_b2[j0 + 1][2] * w2.z + sh_b2[j0 + 1][3] * w2.w
                      + sh_b2[j0 + 1][4] * w3.x + sh_b2[j0 + 1][5] * w3.y
                      + sh_b2[j0 + 1][6] * w3.z + sh_b2[j0 + 1][7] * w3.w;
            float2 bw = *(const float2*)(bw2 + c * HID + j0);
            float2 sc = *(const float2*)(sc2 + c * HID + j0);
            float acc = sh_h2[j0] * bw.x + sp0 * sc.x
                      + sh_h2[j0 + 1] * bw.y + sp1 * sc.y;
#pragma unroll
            for (int off = 16; off >= 1; off >>= 1)
                acc += __shfl_xor_sync(0xffffffffu, acc, off);
            if (lane == 0)
                gate[b * CIN + c] = 1.0f / (1.0f + __expf(-acc));
        }
    }
}

// ---------------------------------------------------------------------------
// Kernel 3: out = x * gate. One block per plane, loads front-batched.
// ---------------------------------------------------------------------------
__global__ void __launch_bounds__(256) apply_kernel(const float4* __restrict__ x,
                                                    const float* __restrict__ gate,
                                                    float4* __restrict__ out) {
    const int plane = blockIdx.x;
    const float g = __ldg(gate + plane);
    const float4* p = x + (size_t)plane * (PLANE / 4);
    float4* q = out + (size_t)plane * (PLANE / 4);
    float4 v0 = p[threadIdx.x];
    float4 v1 = p[256 + threadIdx.x];
    float4 v2 = p[512 + threadIdx.x];
    float4 v3 = p[768 + threadIdx.x];
    v0.x *= g; v0.y *= g; v0.z *= g; v0.w *= g;
    v1.x *= g; v1.y *= g; v1.z *= g; v1.w *= g;
    v2.x *= g; v2.y *= g; v2.z *= g; v2.w *= g;
    v3.x *= g; v3.y *= g; v3.z *= g; v3.w *= g;
    q[threadIdx.x] = v0;
    q[256 + threadIdx.x] = v1;
    q[512 + threadIdx.x] = v2;
    q[768 + threadIdx.x] = v3;
}

extern "C" void kernel_launch(void* const* d_in, const int* in_sizes, int n_in,
                              void* d_out, int out_size) {
    const float* x     = (const float*)d_in[0];
    const float* grid1 = (const float*)d_in[1];
    const float* bw1   = (const float*)d_in[2];
    const float* sw1   = (const float*)d_in[3];
    const float* sc1   = (const float*)d_in[4];
    const float* grid2 = (const float*)d_in[5];
    const float* bw2   = (const float*)d_in[6];
    const float* sw2   = (const float*)d_in[7];
    const float* sc2   = (const float*)d_in[8];
    float* out = (float*)d_out;

    float *s_buf, *gate_buf;
    cudaGetSymbolAddress((void**)&s_buf, g_s);
    cudaGetSymbolAddress((void**)&gate_buf, g_gate);

    const int nplanes = BATCH * CIN;  // 16384

    mean_kernel<<<nplanes, 256>>>((const float4*)x, s_buf);
    kan_fused_kernel<<<BATCH, 512>>>(s_buf, grid1, bw1, sw1, sc1,
                                     grid2, bw2, sw2, sc2, gate_buf);
    apply_kernel<<<nplanes, 256>>>((const float4*)x, gate_buf, (float4*)out);
}

// round 4
// speedup vs baseline: 1.0909x; 1.0909x over previous
#include <cuda_runtime.h>
#include <math.h>

#define BATCH 32
#define CIN 512
#define HID 64
#define PLANE 4096            // 64*64 floats per (b,c) plane
#define PLANE4 1024           // float4s per plane
#define NKNOT 12
#define NBASE 8
#define NPLANES (BATCH * CIN) // 16384

#define NBLOCKS 296
#define NTHREADS 512
#define NWARPS (NBLOCKS * (NTHREADS / 32))   // 4736

// Scratch (no device allocations allowed)
__device__ float g_silu[BATCH * CIN];
__device__ float g_bases[BATCH * CIN * NBASE];
__device__ float g_h2silu[BATCH * HID];
__device__ float g_b2[BATCH * HID * NBASE];
__device__ float g_gate[BATCH * CIN];

// Grid barrier state (count always returns to 0; gen monotonic across replays)
__device__ unsigned int g_bar_count = 0;
__device__ volatile unsigned int g_bar_gen = 0;

__device__ __forceinline__ void grid_barrier() {
    __threadfence();
    __syncthreads();
    if (threadIdx.x == 0) {
        unsigned int gen = g_bar_gen;
        unsigned int old = atomicAdd(&g_bar_count, 1u);
        if (old == NBLOCKS - 1) {
            g_bar_count = 0;
            __threadfence();
            g_bar_gen = gen + 1;
        } else {
            while (g_bar_gen == gen) { __nanosleep(64); }
        }
        __threadfence();
    }
    __syncthreads();
}

__device__ __forceinline__ float siluf(float v) {
    return v / (1.0f + __expf(-v));
}

// Cox-de Boor, mirroring the reference recursion. 12 knots -> 8 order-3 bases.
__device__ __forceinline__ void bspline8(float x, const float* t, float* out) {
    float b[11];
#pragma unroll
    for (int j = 0; j < 11; j++)
        b[j] = (x >= t[j] && x < t[j + 1]) ? 1.0f : 0.0f;
#pragma unroll
    for (int k = 1; k <= 3; k++) {
#pragma unroll
        for (int j = 0; j < 10; j++) {
            if (j <= 10 - k) {
                float left  = (x - t[j]) / (t[j + k] - t[j]) * b[j];
                float right = (t[j + k + 1] - x) / (t[j + k + 1] - t[j + 1]) * b[j + 1];
                b[j] = left + right;
            }
        }
    }
#pragma unroll
    for (int j = 0; j < NBASE; j++) out[j] = b[j];
}

__global__ void __launch_bounds__(NTHREADS, 2) kanse_persistent(
    const float4* __restrict__ x,
    const float* __restrict__ grid1, const float* __restrict__ bw1,
    const float* __restrict__ sw1,  const float* __restrict__ sc1,
    const float* __restrict__ grid2, const float* __restrict__ bw2,
    const float* __restrict__ sw2,  const float* __restrict__ sc2,
    float4* __restrict__ out) {

    const int lane = threadIdx.x & 31;
    const int w = blockIdx.x * (NTHREADS / 32) + (threadIdx.x >> 5);

    // ================= Phase 1: plane means + layer-1 prep =================
    for (int plane = w; plane < NPLANES; plane += NWARPS) {
        const float4* p = x + (size_t)plane * PLANE4;
        float sum = 0.0f;
#pragma unroll
        for (int chunk = 0; chunk < 4; chunk++) {
            float4 r[8];
#pragma unroll
            for (int u = 0; u < 8; u++)
                r[u] = p[(chunk * 8 + u) * 32 + lane];
#pragma unroll
            for (int u = 0; u < 8; u++)
                sum += (r[u].x + r[u].y) + (r[u].z + r[u].w);
        }
#pragma unroll
        for (int off = 16; off >= 1; off >>= 1)
            sum += __shfl_xor_sync(0xffffffffu, sum, off);

        if (lane == 0) {
            float m = sum * (1.0f / (float)PLANE);
            if (isnan(m)) m = 0.0f;
            m = fminf(fmaxf(m, -3.402823466e38f), 3.402823466e38f);
            const int c = plane & (CIN - 1);
            float t[NKNOT];
#pragma unroll
            for (int j = 0; j < NKNOT; j++) t[j] = grid1[c * NKNOT + j];
            float bb[NBASE];
            bspline8(m, t, bb);
#pragma unroll
            for (int k = 0; k < NBASE; k++) g_bases[plane * NBASE + k] = bb[k];
            g_silu[plane] = siluf(m);
        }
    }

    grid_barrier();

    // ================= Phase 2a: layer 1 (warp per (b,o)) =================
    if (w < BATCH * HID) {
        const int b = w >> 6;     // 0..31
        const int o = w & (HID - 1);
        const float4* sw4 = (const float4*)(sw1 + (size_t)o * CIN * NBASE);
        const float4* ba4 = (const float4*)(g_bases + (size_t)b * CIN * NBASE);
        const float*  sl  = g_silu + b * CIN;
        const float*  bwr = bw1 + o * CIN;
        const float*  scr = sc1 + o * CIN;

        float acc = 0.0f;
#pragma unroll
        for (int it = 0; it < 16; it++) {
            int c = lane + 32 * it;
            float4 wa = sw4[c * 2];
            float4 wb = sw4[c * 2 + 1];
            float4 ca = ba4[c * 2];
            float4 cb = ba4[c * 2 + 1];
            float sp = ca.x * wa.x + ca.y * wa.y + ca.z * wa.z + ca.w * wa.w
                     + cb.x * wb.x + cb.y * wb.y + cb.z * wb.z + cb.w * wb.w;
            acc += sl[c] * bwr[c] + sp * scr[c];
        }
#pragma unroll
        for (int off = 16; off >= 1; off >>= 1)
            acc += __shfl_xor_sync(0xffffffffu, acc, off);

        if (lane == 0) {
            float h = siluf(acc);
            g_h2silu[b * HID + o] = siluf(h);
            float t[NKNOT];
#pragma unroll
            for (int j = 0; j < NKNOT; j++) t[j] = grid2[o * NKNOT + j];
            float bb2[NBASE];
            bspline8(h, t, bb2);
#pragma unroll
            for (int k = 0; k < NBASE; k++)
                g_b2[(b * HID + o) * NBASE + k] = bb2[k];
        }
    }

    grid_barrier();

    // ================= Phase 2b: layer 2 + sigmoid (warp per (b,c)) ========
    for (int t = w; t < BATCH * CIN; t += NWARPS) {
        const int b = t >> 9;       // 0..31
        const int c = t & (CIN - 1);
        const int j0 = lane * 2;    // lane covers hidden j0, j0+1
        const float4* sw4 = (const float4*)(sw2 + (size_t)c * HID * NBASE);
        const float4* b24 = (const float4*)(g_b2 + (size_t)b * HID * NBASE);

        float4 w0 = sw4[j0 * 2];
        float4 w1 = sw4[j0 * 2 + 1];
        float4 w2 = sw4[j0 * 2 + 2];
        float4 w3 = sw4[j0 * 2 + 3];
        float4 c0 = b24[j0 * 2];
        float4 c1 = b24[j0 * 2 + 1];
        float4 c2 = b24[j0 * 2 + 2];
        float4 c3 = b24[j0 * 2 + 3];
        float sp0 = c0.x * w0.x + c0.y * w0.y + c0.z * w0.z + c0.w * w0.w
                  + c1.x * w1.x + c1.y * w1.y + c1.z * w1.z + c1.w * w1.w;
        float sp1 = c2.x * w2.x + c2.y * w2.y + c2.z * w2.z + c2.w * w2.w
                  + c3.x * w3.x + c3.y * w3.y + c3.z * w3.z + c3.w * w3.w;
        float2 bw = *(const float2*)(bw2 + c * HID + j0);
        float2 sc = *(const float2*)(sc2 + c * HID + j0);
        float2 h2 = *(const float2*)(g_h2silu + b * HID + j0);
        float acc = h2.x * bw.x + sp0 * sc.x + h2.y * bw.y + sp1 * sc.y;
#pragma unroll
        for (int off = 16; off >= 1; off >>= 1)
            acc += __shfl_xor_sync(0xffffffffu, acc, off);
        if (lane == 0)
            g_gate[t] = 1.0f / (1.0f + __expf(-acc));
    }

    grid_barrier();

    // ================= Phase 3: out = x * gate =============================
    for (int plane = w; plane < NPLANES; plane += NWARPS) {
        const float g = g_gate[plane];
        const float4* p = x + (size_t)plane * PLANE4;
        float4* q = out + (size_t)plane * PLANE4;
#pragma unroll
        for (int chunk = 0; chunk < 4; chunk++) {
            float4 r[8];
#pragma unroll
            for (int u = 0; u < 8; u++)
                r[u] = p[(chunk * 8 + u) * 32 + lane];
#pragma unroll
            for (int u = 0; u < 8; u++) {
                r[u].x *= g; r[u].y *= g; r[u].z *= g; r[u].w *= g;
                q[(chunk * 8 + u) * 32 + lane] = r[u];
            }
        }
    }
}

extern "C" void kernel_launch(void* const* d_in, const int* in_sizes, int n_in,
                              void* d_out, int out_size) {
    const float* x     = (const float*)d_in[0];
    const float* grid1 = (const float*)d_in[1];
    const float* bw1   = (const float*)d_in[2];
    const float* sw1   = (const float*)d_in[3];
    const float* sc1   = (const float*)d_in[4];
    const float* grid2 = (const float*)d_in[5];
    const float* bw2   = (const float*)d_in[6];
    const float* sw2   = (const float*)d_in[7];
    const float* sc2   = (const float*)d_in[8];
    float* out = (float*)d_out;

    kanse_persistent<<<NBLOCKS, NTHREADS>>>(
        (const float4*)x, grid1, bw1, sw1, sc1,
        grid2, bw2, sw2, sc2, (float4*)out);
}